// round 3
// baseline (speedup 1.0000x reference)
#include <cuda_runtime.h>
#include <cuda_fp16.h>
#include <cstdint>

#define NTH     512
#define PT      128
#define NPT     78
#define NTILES  (128 * NPT)
#define PLEN    9984
#define LL      10000
#define NK      128

// smem layout (bytes); W/V 1024B-aligned
#define XS_OFF  0            // 145 float4 (we load 144, +pad)
#define W_OFF   3072         // 64KB: W'[k][s] fp16, blocked SW128
#define V_OFF   68608        // 64KB: V[p][s] fp16, blocked SW128
#define SMEM_TOTAL 134144

static __device__ __forceinline__ uint32_t s2u(const void* p) {
    uint32_t a;
    asm("{ .reg .u64 t; cvta.to.shared.u64 t, %1; cvt.u32.u64 %0, t; }" : "=r"(a) : "l"(p));
    return a;
}

// Blocked SW128 atom layout for a [rows x 256 halves] fp16 matrix.
// atom = 8 rows x 128B; atom_off = (row>>3) + (s>>6)*16; swizzle XOR bits[6:4] ^= row&7.
static __device__ __forceinline__ uint32_t vw_addr(int row, int s) {
    uint32_t byte = (uint32_t)((((row >> 3) + ((s >> 6) << 4)) << 10) + ((row & 7) << 7) + ((s & 63) << 1));
    return byte ^ ((byte >> 3) & 0x70);
}

static __device__ __forceinline__ uint32_t f2h2(float a, float b) {
    __half2 h = __floats2half2_rn(a, b);
    return *reinterpret_cast<uint32_t*>(&h);
}

static __device__ __forceinline__ void ldsm4(uint32_t (&r)[4], uint32_t addr) {
    asm volatile("ldmatrix.sync.aligned.m8n8.x4.shared.b16 {%0,%1,%2,%3}, [%4];"
        : "=r"(r[0]), "=r"(r[1]), "=r"(r[2]), "=r"(r[3]) : "r"(addr));
}

static __device__ __forceinline__ void mma16816(float (&d)[4], const uint32_t (&a)[4],
                                                uint32_t b0, uint32_t b1) {
    asm volatile("mma.sync.aligned.m16n8k16.row.col.f32.f16.f16.f32 "
        "{%0,%1,%2,%3}, {%4,%5,%6,%7}, {%8,%9}, {%0,%1,%2,%3};"
        : "+f"(d[0]), "+f"(d[1]), "+f"(d[2]), "+f"(d[3])
        : "r"(a[0]), "r"(a[1]), "r"(a[2]), "r"(a[3]), "r"(b0), "r"(b1));
}

__global__ void __launch_bounds__(NTH, 1)
markonv_kernel(const float* __restrict__ x, const float* __restrict__ ker,
               float* __restrict__ out) {
    extern __shared__ char smem[];
    uint32_t sb = s2u(smem);
    const int tid = threadIdx.x;
    const int lane = tid & 31;
    const int wid = tid >> 5;
    const int wm = wid & 3;   // warp M (k) index: 4 x 32 rows
    const int wn = wid >> 2;  // warp N (p) index: 4 x 32 cols

    // ---- stage W once per CTA: W'[k][s] = ker[s*128 + k], fp16, swizzled ----
    // ker shape [16,4,4,128] row-major => linear = s*128 + k.
    for (int idx = tid; idx < 128 * 128; idx += NTH) {
        int k = idx & 127, s = (idx >> 7) << 1;   // coalesced over k
        *(uint32_t*)(smem + W_OFF + vw_addr(k, s)) =
            f2h2(ker[s * 128 + k], ker[s * 128 + 128 + k]);
    }

    float4* xs4 = (float4*)(smem + XS_OFF);

    // per-thread ldmatrix addresses (s-part added per k-step)
    // A (W): rows = m = wm*32 + frag*16 + (lane&15); k-chunk from lane>>4
    const int a_row0 = wm * 32 + (lane & 15);
    const int a_schunk = (lane >> 4) << 3;
    // B (V): rows = n = wn*32 + frag*16 + (lane&7) + ((lane>>4)<<3); k-chunk from (lane>>3)&1
    const int b_row0 = wn * 32 + (lane & 7) + ((lane >> 4) << 3);
    const int b_schunk = ((lane >> 3) & 1) << 3;

    for (int tile = blockIdx.x; tile < NTILES; tile += gridDim.x) {
        const int b = tile / NPT;
        const int p0 = (tile - b * NPT) * PT;

        // ---- stage x window: 144 positions x 4ch ----
        const float4* xg = (const float4*)(x + ((size_t)b * LL + p0) * 4);
        for (int idx = tid; idx < 144; idx += NTH) xs4[idx] = xg[idx];
        __syncthreads();

        // ---- build V[p][i*16 + c1*4 + c2] = x[p+i][c1]*x[p+i+1][c2] (fp16) ----
        for (int u = tid; u < 2048; u += NTH) {
            const int i = u >> 7, p = u & 127, t = p + i;
            const float4 a = xs4[t], c = xs4[t + 1];
            const int s0 = i << 4;
            char* vb = smem + V_OFF;
            uint4 lo, hi;
            lo.x = f2h2(a.x * c.x, a.x * c.y); lo.y = f2h2(a.x * c.z, a.x * c.w);
            lo.z = f2h2(a.y * c.x, a.y * c.y); lo.w = f2h2(a.y * c.z, a.y * c.w);
            hi.x = f2h2(a.z * c.x, a.z * c.y); hi.y = f2h2(a.z * c.z, a.z * c.w);
            hi.z = f2h2(a.w * c.x, a.w * c.y); hi.w = f2h2(a.w * c.z, a.w * c.w);
            *(uint4*)(vb + vw_addr(p, s0))     = lo;
            *(uint4*)(vb + vw_addr(p, s0 + 8)) = hi;
        }
        __syncthreads();

        // ---- GEMM: D[128k x 128p] = W[128k x 256] * V^T ----
        float acc[2][4][4];
        #pragma unroll
        for (int mf = 0; mf < 2; mf++)
            #pragma unroll
            for (int nf = 0; nf < 4; nf++)
                #pragma unroll
                for (int e = 0; e < 4; e++) acc[mf][nf][e] = 0.f;

        #pragma unroll
        for (int ks = 0; ks < 16; ks++) {
            const int s = ks << 4;
            uint32_t af[2][4], bf[2][4];
            ldsm4(af[0], sb + W_OFF + vw_addr(a_row0,      s + a_schunk));
            ldsm4(af[1], sb + W_OFF + vw_addr(a_row0 + 16, s + a_schunk));
            ldsm4(bf[0], sb + V_OFF + vw_addr(b_row0,      s + b_schunk));
            ldsm4(bf[1], sb + V_OFF + vw_addr(b_row0 + 16, s + b_schunk));
            #pragma unroll
            for (int mf = 0; mf < 2; mf++)
                #pragma unroll
                for (int nf = 0; nf < 4; nf++)
                    mma16816(acc[mf][nf], af[mf], bf[nf >> 1][(nf & 1) * 2],
                             bf[nf >> 1][(nf & 1) * 2 + 1]);
        }
        __syncthreads();  // V/XS may be rewritten next iteration

        // ---- epilogue: direct STG.64, rows = k, cols = consecutive p ----
        {
            const size_t obase = ((size_t)b * NK + wm * 32) * PLEN + p0 + wn * 32;
            const int krow = lane >> 2;
            const int pcol = (lane & 3) * 2;
            #pragma unroll
            for (int mf = 0; mf < 2; mf++) {
                #pragma unroll
                for (int nf = 0; nf < 4; nf++) {
                    float2 v0 = make_float2(acc[mf][nf][0], acc[mf][nf][1]);
                    float2 v1 = make_float2(acc[mf][nf][2], acc[mf][nf][3]);
                    size_t o = obase + (size_t)(mf * 16 + krow) * PLEN + nf * 8 + pcol;
                    *(float2*)(out + o)             = v0;   // row krow
                    *(float2*)(out + o + 8 * PLEN)  = v1;   // row krow+8
                }
            }
        }
    }
}

extern "C" void kernel_launch(void* const* d_in, const int* in_sizes, int n_in,
                              void* d_out, int out_size) {
    static int nsm = 0;
    if (nsm == 0) {
        int dev = 0;
        cudaGetDevice(&dev);
        if (cudaDeviceGetAttribute(&nsm, cudaDevAttrMultiProcessorCount, dev) != cudaSuccess || nsm <= 0)
            nsm = 148;
        cudaFuncSetAttribute(markonv_kernel, cudaFuncAttributeMaxDynamicSharedMemorySize, SMEM_TOTAL);
    }
    markonv_kernel<<<nsm, NTH, SMEM_TOTAL>>>(
        (const float*)d_in[0], (const float*)d_in[1], (float*)d_out);
}